// round 9
// baseline (speedup 1.0000x reference)
#include <cuda_runtime.h>
#include <cuda_bf16.h>
#include <cstdint>

// ---------------------------------------------------------------------------
// MatchingNetwork — Round 9: DUAL-PIPE hybrid GEMM.
//   K[0,9600):     3 slices, split-bf16 3-term HMMA (R3 kernel, proven 205us)
//   K[9600,20000): 4 slices, fp32 FFMA2 (f32x2) path on the fma pipe
// Both CTA types co-resident -> tensor pipe and fma pipe run in parallel.
// ---------------------------------------------------------------------------

#define B_SZ   256
#define S_SZ   20
#define V_SZ   20000
#define C_SZ   20
#define D_SZ   64
#define M_SUP  (B_SZ * S_SZ)      // 5120
#define M_ALL  (M_SUP + B_SZ)     // 5376
#define KSPLIT 7                  // 3 tensor + 4 fp32 slices in g_part

// ---- tensor path (R3 geometry) ----
#define T_STEPS 200               // k16 steps per tensor slice (3 x 3200 elems)
#define T_NCH   40                // chunks of 5 steps (80 elems), no partials
#define PITCH   176u
#define OF_ALO  22528u            // 128*176
#define OF_BHI  45056u
#define OF_BLO  56320u
#define SMEM_TOTAL 67584

// ---- fp32 path ----
#define F_BASE  9600
#define F_LEN   2600              // per slice
#define F_KB    40                // k-chunk
#define F_NCH   65                // 2600/40, no partials
#define F_APITCH 528u             // dup-A row pitch bytes (40 k rows)
#define F_ASZ    21120u           // 40*528
#define F_BPITCH 272u             // B row pitch (64 floats + pad)
#define F_BUF    32000u           // F_ASZ + 40*272, per buffer

typedef uint32_t u32;
typedef unsigned long long ull;

// ---- device scratch ---------------------------------------------------------
__device__ float         g_part[(size_t)KSPLIT * M_ALL * D_SZ];
__device__ float         g_sup[(size_t)M_ALL * D_SZ];
__device__ __nv_bfloat16 g_Whi[(size_t)D_SZ * V_SZ];
__device__ __nv_bfloat16 g_Wlo[(size_t)D_SZ * V_SZ];
__device__ float         g_Wt[(size_t)V_SZ * D_SZ];   // transposed W
__device__ float         g_pb[2 * B_SZ];

// ---- PTX helpers ------------------------------------------------------------
__device__ __forceinline__ u32 smem_u32(const void* p) {
    u32 a;
    asm("{ .reg .u64 t; cvta.to.shared.u64 t, %1; cvt.u32.u64 %0, t; }"
        : "=r"(a) : "l"(p));
    return a;
}
__device__ __forceinline__ void sts32(u32 a, u32 v) {
    asm volatile("st.shared.b32 [%0], %1;" :: "r"(a), "r"(v));
}
__device__ __forceinline__ void cp16(u32 s, const void* g) {
    asm volatile("cp.async.cg.shared.global [%0], [%1], 16;" :: "r"(s), "l"(g));
}
#define CP_COMMIT() asm volatile("cp.async.commit_group;" ::: "memory")
#define CP_WAIT0()  asm volatile("cp.async.wait_group 0;" ::: "memory")

__device__ __forceinline__ void ldm4(u32 a, u32 r[4]) {
    asm volatile("ldmatrix.sync.aligned.m8n8.x4.shared.b16 {%0,%1,%2,%3}, [%4];"
        : "=r"(r[0]), "=r"(r[1]), "=r"(r[2]), "=r"(r[3]) : "r"(a));
}
__device__ __forceinline__ void mma16816(float c[4], const u32 a[4],
                                         const u32* b) {
    asm volatile("mma.sync.aligned.m16n8k16.row.col.f32.bf16.bf16.f32 "
        "{%0,%1,%2,%3}, {%4,%5,%6,%7}, {%8,%9}, {%0,%1,%2,%3};"
        : "+f"(c[0]), "+f"(c[1]), "+f"(c[2]), "+f"(c[3])
        : "r"(a[0]), "r"(a[1]), "r"(a[2]), "r"(a[3]), "r"(b[0]), "r"(b[1]));
}
__device__ __forceinline__ u32 cvt2bf(float lo, float hi) {
    u32 r;
    asm("cvt.rn.bf16x2.f32 %0, %1, %2;" : "=r"(r) : "f"(hi), "f"(lo));
    return r;
}
__device__ __forceinline__ ull fma2(ull a, ull b, ull c) {
    ull d;
    asm("fma.rn.f32x2 %0, %1, %2, %3;" : "=l"(d) : "l"(a), "l"(b), "l"(c));
    return d;
}
__device__ __forceinline__ float2 unpack2(ull v) {
    float2 r;
    asm("mov.b64 {%0, %1}, %2;" : "=f"(r.x), "=f"(r.y) : "l"(v));
    return r;
}

// ---- K0: build bf16 hi/lo split AND fp32 transpose ----------------------------
__global__ void prep_w_kernel(const float* __restrict__ W) {
    int idx = blockIdx.x * 256 + threadIdx.x;          // covers D*V exactly
    float x  = W[idx];
    __nv_bfloat16 h = __float2bfloat16_rn(x);
    g_Whi[idx] = h;
    g_Wlo[idx] = __float2bfloat16_rn(x - __bfloat162float(h));
    int d = idx / V_SZ;
    int v = idx - d * V_SZ;
    g_Wt[(size_t)v * D_SZ + d] = x;
}

// ---- K1: hybrid GEMM -----------------------------------------------------------
// grid = 462 blocks, 128 threads.
//   bx < 126 : tensor CTA  (m-tile of 128 rows = bx/3, tensor slice = bx%3)
//   else     : fp32 CTA    (m-tile of 64 rows, fp32 slice 0..3)
__global__ __launch_bounds__(128) void gemm_kernel(
    const float* __restrict__ img, const float* __restrict__ tgtim)
{
    extern __shared__ char smem[];
    const u32 sb = smem_u32(smem);
    const int tid  = threadIdx.x;
    const int lane = tid & 31;

    if (blockIdx.x < 126) {
        // ==================== TENSOR PATH (R3, 3-term split-bf16) ====================
        const int w    = tid >> 5;
        const int mt   = blockIdx.x / 3;
        const int ks   = blockIdx.x - mt * 3;
        const int row0 = mt * 128;
        const int sbeg = ks * T_STEPS;                 // k16 units

        const float* abase = (mt < 40)
            ? img   + (size_t)row0 * V_SZ
            : tgtim + (size_t)(row0 - M_SUP) * V_SZ;

        const int arow_l = tid >> 3;        // 0..15 (+16*pass)
        const int atc    = tid & 7;
        const int brow   = tid >> 1;        // 0..63
        const int bhalf  = tid & 1;

        const u32 aLB = (u32)(w * 32 + (lane & 15)) * PITCH
                      + (u32)((lane >> 4) * 16);
        const u32 bLB = (u32)((lane & 7) + ((lane >> 4) & 1) * 8) * PITCH
                      + (u32)(((lane >> 3) & 1) * 16);

        float acc[2][8][4];
        #pragma unroll
        for (int mt2 = 0; mt2 < 2; ++mt2)
            #pragma unroll
            for (int nt = 0; nt < 8; ++nt)
                #pragma unroll
                for (int i = 0; i < 4; ++i) acc[mt2][nt][i] = 0.f;

        for (int c = 0; c < T_NCH; ++c) {
            const int k0 = (sbeg + c * 5) * 16;

            __syncthreads();

            // B tiles via cp.async
            {
                const char* gh = (const char*)(g_Whi + (size_t)brow * V_SZ + k0);
                const char* gl = (const char*)(g_Wlo + (size_t)brow * V_SZ + k0);
                u32 sB = sb + (u32)brow * PITCH;
                #pragma unroll
                for (int j = 0; j < 5; ++j) {
                    int piece = bhalf * 5 + j;
                    cp16(sB + OF_BHI + piece * 16, gh + piece * 16);
                    cp16(sB + OF_BLO + piece * 16, gl + piece * 16);
                }
                CP_COMMIT();
            }
            // A tiles: LDG fp32 -> split bf16 hi/lo -> STS
            #pragma unroll
            for (int p = 0; p < 8; ++p) {
                const int rl = arow_l + p * 16;
                const float2* rp = (const float2*)(abase + (size_t)rl * V_SZ + k0);
                u32 sA = sb + (u32)rl * PITCH;
                #pragma unroll
                for (int j = 0; j < 5; ++j) {
                    const int c2 = j * 8 + atc;
                    float2 v = rp[c2];
                    u32 h = cvt2bf(v.x, v.y);
                    float r0 = v.x - __uint_as_float(h << 16);
                    float r1 = v.y - __uint_as_float(h & 0xFFFF0000u);
                    u32 l = cvt2bf(r0, r1);
                    sts32(sA + c2 * 4,          h);
                    sts32(sA + OF_ALO + c2 * 4, l);
                }
            }

            CP_WAIT0();
            __syncthreads();

            // MMA over 5 k16-steps
            #pragma unroll
            for (int s = 0; s < 5; ++s) {
                const u32 sbyte = (u32)s * 32;
                u32 ah[2][4], al[2][4];
                #pragma unroll
                for (int m2 = 0; m2 < 2; ++m2) {
                    u32 a = sb + aLB + (u32)m2 * (16 * PITCH) + sbyte;
                    ldm4(a,          ah[m2]);
                    ldm4(a + OF_ALO, al[m2]);
                }
                #pragma unroll
                for (int q = 0; q < 4; ++q) {
                    u32 bh[4], bl[4];
                    u32 a = sb + bLB + (u32)q * (16 * PITCH) + sbyte;
                    ldm4(a + OF_BHI, bh);
                    ldm4(a + OF_BLO, bl);
                    #pragma unroll
                    for (int m2 = 0; m2 < 2; ++m2)
                        #pragma unroll
                        for (int h = 0; h < 2; ++h) {
                            float* cc = acc[m2][q * 2 + h];
                            mma16816(cc, ah[m2], &bh[2 * h]);
                            mma16816(cc, ah[m2], &bl[2 * h]);
                            mma16816(cc, al[m2], &bh[2 * h]);
                        }
                }
            }
        }

        // epilogue: store fp32 partials into slice ks
        const int r4 = lane >> 2, c4 = lane & 3;
        #pragma unroll
        for (int m2 = 0; m2 < 2; ++m2) {
            const size_t rg = (size_t)row0 + w * 32 + m2 * 16 + r4;
            float* base = &g_part[((size_t)ks * M_ALL + rg) * D_SZ];
            #pragma unroll
            for (int nt = 0; nt < 8; ++nt) {
                *(float2*)(base + nt * 8 + c4 * 2) =
                    make_float2(acc[0 + m2][nt][0], acc[m2][nt][1]);
                *(float2*)(base + 8 * (size_t)D_SZ + nt * 8 + c4 * 2) =
                    make_float2(acc[m2][nt][2], acc[m2][nt][3]);
            }
        }
    } else {
        // ==================== FP32 PATH (FFMA2 / f32x2, fma pipe) ====================
        const int i    = blockIdx.x - 126;
        const int mt   = i >> 2;                       // 0..83, 64-row tiles
        const int ksf  = i & 3;                        // fp32 slice 0..3
        const int row0 = mt * 64;
        const int kbase = F_BASE + ksf * F_LEN;

        const float* abase = (mt < 80)
            ? img   + (size_t)row0 * V_SZ
            : tgtim + (size_t)(row0 - M_SUP) * V_SZ;

        const int tm = tid >> 3;            // 0..15 -> rows tm*4..+3
        const int tn = tid & 7;             // cols tn*8..+7
        // A loader: 8 threads/row over 16 rows/pass, 4 passes
        const int arow = tid >> 3;          // 0..15
        const int ac   = tid & 7;           // float4 idx (0..7), extras at 8+ac for ac<2

        ull acc[4][4];
        #pragma unroll
        for (int r = 0; r < 4; ++r)
            #pragma unroll
            for (int j = 0; j < 4; ++j) acc[r][j] = 0ull;

        float4 st[4], stx[4];
        const bool extra = (ac < 2);

        // ---- helpers as lambdas (inlined) ----
        // prologue: chunk 0
        {
            const int k0 = kbase;
            #pragma unroll
            for (int p = 0; p < 4; ++p) {
                const float* rp = abase + (size_t)(arow + 16 * p) * V_SZ + k0;
                st[p] = *(const float4*)(rp + ac * 4);
                if (extra) stx[p] = *(const float4*)(rp + 32 + ac * 4);
            }
            // B: 640 cp16 pieces
            #pragma unroll
            for (int j = 0; j < 5; ++j) {
                int piece = tid + 128 * j;
                int krow = piece >> 4, seg = piece & 15;
                cp16(sb + F_ASZ + (u32)krow * F_BPITCH + (u32)seg * 16,
                     g_Wt + (size_t)(k0 + krow) * D_SZ + seg * 4);
            }
            CP_COMMIT();
            // STS duplicated pairs
            #pragma unroll
            for (int p = 0; p < 4; ++p) {
                const u32 rb = sb + (u32)(arow + 16 * p) * 8u;
                const float* f = (const float*)&st[p];
                #pragma unroll
                for (int q = 0; q < 4; ++q) {
                    u32 ka = (u32)(ac * 4 + q) * F_APITCH;
                    asm volatile("st.shared.v2.f32 [%0], {%1, %1};"
                                 :: "r"(rb + ka), "f"(f[q]));
                }
                if (extra) {
                    const float* g = (const float*)&stx[p];
                    #pragma unroll
                    for (int q = 0; q < 4; ++q) {
                        u32 ka = (u32)(32 + ac * 4 + q) * F_APITCH;
                        asm volatile("st.shared.v2.f32 [%0], {%1, %1};"
                                     :: "r"(rb + ka), "f"(g[q]));
                    }
                }
            }
            CP_WAIT0();
        }
        __syncthreads();

        for (int it = 0; it < F_NCH; ++it) {
            const u32 bb = (u32)(it & 1) * F_BUF;
            const u32 nb = bb ^ F_BUF;
            const bool more = (it + 1 < F_NCH);

            if (more) {
                const int k0 = kbase + (it + 1) * F_KB;
                #pragma unroll
                for (int p = 0; p < 4; ++p) {
                    const float* rp = abase + (size_t)(arow + 16 * p) * V_SZ + k0;
                    st[p] = *(const float4*)(rp + ac * 4);
                    if (extra) stx[p] = *(const float4*)(rp + 32 + ac * 4);
                }
                #pragma unroll
                for (int j = 0; j < 5; ++j) {
                    int piece = tid + 128 * j;
                    int krow = piece >> 4, seg = piece & 15;
                    cp16(sb + nb + F_ASZ + (u32)krow * F_BPITCH + (u32)seg * 16,
                         g_Wt + (size_t)(k0 + krow) * D_SZ + seg * 4);
                }
                CP_COMMIT();
            }

            // compute 40 k-steps on current buffer
            const char* Abase = smem + bb + (u32)tm * 32u;
            const char* Bbase = smem + bb + F_ASZ + (u32)tn * 32u;
            #pragma unroll 4
            for (int k = 0; k < F_KB; ++k) {
                const ulonglong2* A16 =
                    (const ulonglong2*)(Abase + (u32)k * F_APITCH);
                const ulonglong2* B16 =
                    (const ulonglong2*)(Bbase + (u32)k * F_BPITCH);
                ulonglong2 aA = A16[0];     // (a0,a0),(a1,a1)
                ulonglong2 aB = A16[1];     // (a2,a2),(a3,a3)
                ulonglong2 b0 = B16[0];     // (b0,b1),(b2,b3)
                ulonglong2 b1 = B16[1];     // (b4,b5),(b6,b7)
                acc[0][0] = fma2(aA.x, b0.x, acc[0][0]);
                acc[0][1] = fma2(aA.x, b0.y, acc[0][1]);
                acc[0][2] = fma2(aA.x, b1.x, acc[0][2]);
                acc[0][3] = fma2(aA.x, b1.y, acc[0][3]);
                acc[1][0] = fma2(aA.y, b0.x, acc[1][0]);
                acc[1][1] = fma2(aA.y, b0.y, acc[1][1]);
                acc[1][2] = fma2(aA.y, b1.x, acc[1][2]);
                acc[1][3] = fma2(aA.y, b1.y, acc[1][3]);
                acc[2][0] = fma2(aB.x, b0.x, acc[2][0]);
                acc[2][1] = fma2(aB.x, b0.y, acc[2][1]);
                acc[2][2] = fma2(aB.x, b1.x, acc[2][2]);
                acc[2][3] = fma2(aB.x, b1.y, acc[2][3]);
                acc[3][0] = fma2(aB.y, b0.x, acc[3][0]);
                acc[3][1] = fma2(aB.y, b0.y, acc[3][1]);
                acc[3][2] = fma2(aB.y, b1.x, acc[3][2]);
                acc[3][3] = fma2(aB.y, b1.y, acc[3][3]);
            }

            if (more) {
                #pragma unroll
                for (int p = 0; p < 4; ++p) {
                    const u32 rb = sb + nb + (u32)(arow + 16 * p) * 8u;
                    const float* f = (const float*)&st[p];
                    #pragma unroll
                    for (int q = 0; q < 4; ++q) {
                        u32 ka = (u32)(ac * 4 + q) * F_APITCH;
                        asm volatile("st.shared.v2.f32 [%0], {%1, %1};"
                                     :: "r"(rb + ka), "f"(f[q]));
                    }
                    if (extra) {
                        const float* g = (const float*)&stx[p];
                        #pragma unroll
                        for (int q = 0; q < 4; ++q) {
                            u32 ka = (u32)(32 + ac * 4 + q) * F_APITCH;
                            asm volatile("st.shared.v2.f32 [%0], {%1, %1};"
                                         :: "r"(rb + ka), "f"(g[q]));
                        }
                    }
                }
            }
            CP_WAIT0();
            __syncthreads();
        }

        // epilogue: store fp32 partials into slice 3+ksf
        #pragma unroll
        for (int r = 0; r < 4; ++r) {
            float* base = &g_part[((size_t)(3 + ksf) * M_ALL
                                   + row0 + tm * 4 + r) * D_SZ + tn * 8];
            float2 f0 = unpack2(acc[r][0]);
            float2 f1 = unpack2(acc[r][1]);
            float2 f2 = unpack2(acc[r][2]);
            float2 f3 = unpack2(acc[r][3]);
            *(float4*)(base)     = make_float4(f0.x, f0.y, f1.x, f1.y);
            *(float4*)(base + 4) = make_float4(f2.x, f2.y, f3.x, f3.y);
        }
    }
}

// ---- K2: reduce k-slices + bias -> g_sup --------------------------------------
__global__ void reduce_kernel(const float* __restrict__ bias) {
    int idx = blockIdx.x * 256 + threadIdx.x;       // covers M_ALL*D exactly
    float s = bias[idx & 63];
    #pragma unroll
    for (int ks = 0; ks < KSPLIT; ++ks)
        s += g_part[(size_t)ks * M_ALL * D_SZ + idx];
    g_sup[idx] = s;
}

// ---- K3: warp-per-episode sims/softmax/preds/argmax/CE ------------------------
__global__ void sim_kernel(const float* __restrict__ onehot,
                           const int* __restrict__ tgty)
{
    const int b    = blockIdx.x;                    // 256 blocks, 32 threads
    const int lane = threadIdx.x;
    const unsigned FULL = 0xFFFFFFFFu;

    const float4* t4 = (const float4*)&g_sup[(size_t)(M_SUP + b) * D_SZ];
    float sim = -3.0e38f;
    if (lane < S_SZ) {
        const float4* s4 = (const float4*)&g_sup[(size_t)(b * S_SZ + lane) * D_SZ];
        float d0 = 0.f, d1 = 0.f, d2 = 0.f, d3 = 0.f;
        float m0 = 0.f, m1 = 0.f, m2 = 0.f, m3 = 0.f;
        #pragma unroll
        for (int i = 0; i < 16; ++i) {
            float4 s = s4[i], t = t4[i];
            d0 += s.x * t.x; d1 += s.y * t.y; d2 += s.z * t.z; d3 += s.w * t.w;
            m0 += s.x * s.x; m1 += s.y * s.y; m2 += s.z * s.z; m3 += s.w * s.w;
        }
        float dot = (d0 + d1) + (d2 + d3);
        float mag = (m0 + m1) + (m2 + m3);
        sim = dot * rsqrtf(fmaxf(mag, 1e-10f));
    }
    float m = sim;
    #pragma unroll
    for (int o = 16; o; o >>= 1) m = fmaxf(m, __shfl_xor_sync(FULL, m, o));
    float e = (lane < S_SZ) ? expf(sim - m) : 0.f;
    float sum = e;
    #pragma unroll
    for (int o = 16; o; o >>= 1) sum += __shfl_xor_sync(FULL, sum, o);
    float attn = e / sum;

    float p = 0.f;
    #pragma unroll
    for (int s = 0; s < S_SZ; ++s) {
        float a = __shfl_sync(FULL, attn, s);
        if (lane < C_SZ) p += a * onehot[((size_t)b * S_SZ + s) * C_SZ + lane];
    }

    float bv = (lane < C_SZ) ? p : -3.0e38f;
    int   bi = (lane < C_SZ) ? lane : 999;
    #pragma unroll
    for (int o = 16; o; o >>= 1) {
        float ov = __shfl_xor_sync(FULL, bv, o);
        int   oi = __shfl_xor_sync(FULL, bi, o);
        if (ov > bv || (ov == bv && oi < bi)) { bv = ov; bi = oi; }
    }
    float pm = (lane < C_SZ) ? p : -3.0e38f;
    #pragma unroll
    for (int o = 16; o; o >>= 1) pm = fmaxf(pm, __shfl_xor_sync(FULL, pm, o));
    float ee = (lane < C_SZ) ? expf(p - pm) : 0.f;
    float lse = ee;
    #pragma unroll
    for (int o = 16; o; o >>= 1) lse += __shfl_xor_sync(FULL, lse, o);

    int y = tgty[b];
    float py = __shfl_sync(FULL, p, y);
    if (lane == 0) {
        g_pb[b]        = (bi == y) ? 1.f : 0.f;
        g_pb[B_SZ + b] = -(py - pm - logf(lse));
    }
}

// ---- K4: deterministic final reduction -> d_out -------------------------------
__global__ void finalize_kernel(float* __restrict__ out) {
    __shared__ float sc[B_SZ], sl[B_SZ];
    int t = threadIdx.x;
    sc[t] = g_pb[t];
    sl[t] = g_pb[B_SZ + t];
    __syncthreads();
    for (int off = 128; off > 0; off >>= 1) {
        if (t < off) { sc[t] += sc[t + off]; sl[t] += sl[t + off]; }
        __syncthreads();
    }
    if (t == 0) {
        out[0] = sc[0] * (1.f / (float)B_SZ);
        out[1] = sl[0] * (1.f / (float)B_SZ);
    }
}

// ---------------------------------------------------------------------------
extern "C" void kernel_launch(void* const* d_in, const int* in_sizes, int n_in,
                              void* d_out, int out_size)
{
    const float* img    = (const float*)d_in[0];   // [256,20,20000]
    const float* onehot = (const float*)d_in[1];   // [256,20,20]
    const float* tgtim  = (const float*)d_in[2];   // [256,20000]
    const int*   tgty   = (const int*)  d_in[3];   // [256]
    const float* W      = (const float*)d_in[4];   // [64,20000]
    const float* bias   = (const float*)d_in[5];   // [64]
    float* out = (float*)d_out;                    // [2]

    cudaFuncSetAttribute(gemm_kernel,
                         cudaFuncAttributeMaxDynamicSharedMemorySize, SMEM_TOTAL);

    prep_w_kernel<<<(D_SZ * V_SZ) / 256, 256>>>(W);
    gemm_kernel<<<126 + 336, 128, SMEM_TOTAL>>>(img, tgtim);
    reduce_kernel<<<(M_ALL * D_SZ) / 256, 256>>>(bias);
    sim_kernel<<<B_SZ, 32>>>(onehot, tgty);
    finalize_kernel<<<1, B_SZ>>>(out);
}

// round 11
// speedup vs baseline: 2.2354x; 2.2354x over previous
#include <cuda_runtime.h>
#include <cuda_bf16.h>
#include <cstdint>

// ---------------------------------------------------------------------------
// MatchingNetwork — Round 11: within-warp DUAL-PIPE GEMM (R10 + alignment fix:
// fp32-A smem pitch 104 -> 112 so cp.async 16B dst is 16-aligned).
// Each chunk: 64 K-elems on tensor pipe (3-term split-bf16 HMMA) + 24 K-elems
// on fma pipe (fp32 FFMA2), same warps, same f32x2 accumulators.
// ---------------------------------------------------------------------------

#define B_SZ   256
#define S_SZ   20
#define V_SZ   20000
#define C_SZ   20
#define D_SZ   64
#define M_SUP  (B_SZ * S_SZ)      // 5120
#define M_ALL  (M_SUP + B_SZ)     // 5376
#define KSPLIT 10                 // 10 slices x 2000 K
#define NIT    23                 // tensor chunks (64 elems) per slice
#define NFP    22                 // of which carry a 24-elem fp32 chunk
#define T_LEN  1472               // 23*64 tensor K per slice
#define F_LEN  24                 // fp32 elems per chunk

#define PITCH   144u
#define OF_ALO  18432u            // 128*144
#define OF_BHI  36864u
#define OF_BLO  46080u
#define OF_FA   55296u            // fp32 A: 128 rows x 112B (16-aligned pitch)
#define FA_P    112u
#define OF_FB   69632u            // 55296 + 128*112
#define SMEM_TOTAL 75776          // 69632 + 24*256

typedef uint32_t u32;
typedef unsigned long long ull;

// ---- device scratch ---------------------------------------------------------
__device__ float         g_part[(size_t)KSPLIT * M_ALL * D_SZ];
__device__ float         g_sup[(size_t)M_ALL * D_SZ];
__device__ __nv_bfloat16 g_Whi[(size_t)D_SZ * V_SZ];
__device__ __nv_bfloat16 g_Wlo[(size_t)D_SZ * V_SZ];
__device__ float         g_Wt[(size_t)V_SZ * D_SZ];   // transposed W (fp32)
__device__ float         g_pb[2 * B_SZ];

// ---- PTX helpers ------------------------------------------------------------
__device__ __forceinline__ u32 smem_u32(const void* p) {
    u32 a;
    asm("{ .reg .u64 t; cvta.to.shared.u64 t, %1; cvt.u32.u64 %0, t; }"
        : "=r"(a) : "l"(p));
    return a;
}
__device__ __forceinline__ void cp16(u32 s, const void* g) {
    asm volatile("cp.async.cg.shared.global [%0], [%1], 16;" :: "r"(s), "l"(g));
}
#define CP_COMMIT() asm volatile("cp.async.commit_group;" ::: "memory")
#define CP_WAIT0()  asm volatile("cp.async.wait_group 0;" ::: "memory")

__device__ __forceinline__ void sts64(u32 a, u32 v0, u32 v1) {
    asm volatile("st.shared.v2.b32 [%0], {%1, %2};" :: "r"(a), "r"(v0), "r"(v1));
}
__device__ __forceinline__ void ldm4(u32 a, u32 r[4]) {
    asm volatile("ldmatrix.sync.aligned.m8n8.x4.shared.b16 {%0,%1,%2,%3}, [%4];"
        : "=r"(r[0]), "=r"(r[1]), "=r"(r[2]), "=r"(r[3]) : "r"(a));
}
// HMMA into ull-pair accumulators (c01 = row r cols c,c+1; c23 = row r+8)
__device__ __forceinline__ void mma2(ull& c01, ull& c23, const u32 a[4],
                                     const u32* b) {
    asm volatile("{\n\t.reg .f32 x0,x1,x2,x3;\n\t"
        "mov.b64 {x0,x1}, %0;\n\tmov.b64 {x2,x3}, %1;\n\t"
        "mma.sync.aligned.m16n8k16.row.col.f32.bf16.bf16.f32 "
        "{x0,x1,x2,x3}, {%2,%3,%4,%5}, {%6,%7}, {x0,x1,x2,x3};\n\t"
        "mov.b64 %0, {x0,x1};\n\tmov.b64 %1, {x2,x3};\n\t}"
        : "+l"(c01), "+l"(c23)
        : "r"(a[0]), "r"(a[1]), "r"(a[2]), "r"(a[3]), "r"(b[0]), "r"(b[1]));
}
__device__ __forceinline__ void ffma2(ull& c, ull a, ull b) {
    asm("fma.rn.f32x2 %0, %1, %2, %0;" : "+l"(c) : "l"(a), "l"(b));
}
__device__ __forceinline__ float lds32(u32 a) {
    float v;
    asm volatile("ld.shared.f32 %0, [%1];" : "=f"(v) : "r"(a));
    return v;
}
__device__ __forceinline__ ull lds64(u32 a) {
    ull v;
    asm volatile("ld.shared.b64 %0, [%1];" : "=l"(v) : "r"(a));
    return v;
}
__device__ __forceinline__ ull dup2(float x) {
    ull r;
    asm("mov.b64 %0, {%1, %1};" : "=l"(r) : "f"(x));
    return r;
}
__device__ __forceinline__ float2 unpack2(ull v) {
    float2 r;
    asm("mov.b64 {%0, %1}, %2;" : "=f"(r.x), "=f"(r.y) : "l"(v));
    return r;
}
__device__ __forceinline__ u32 cvt2bf(float lo, float hi) {
    u32 r;
    asm("cvt.rn.bf16x2.f32 %0, %1, %2;" : "=r"(r) : "f"(hi), "f"(lo));
    return r;
}
__device__ __forceinline__ void split4(float4 v, u32& h0, u32& h1,
                                       u32& l0, u32& l1) {
    h0 = cvt2bf(v.x, v.y);
    h1 = cvt2bf(v.z, v.w);
    float r0 = v.x - __uint_as_float(h0 << 16);
    float r1 = v.y - __uint_as_float(h0 & 0xFFFF0000u);
    float r2 = v.z - __uint_as_float(h1 << 16);
    float r3 = v.w - __uint_as_float(h1 & 0xFFFF0000u);
    l0 = cvt2bf(r0, r1);
    l1 = cvt2bf(r2, r3);
}

// ---- K0: W -> bf16 hi/lo + fp32 transpose --------------------------------------
__global__ void prep_w_kernel(const float* __restrict__ W) {
    int idx = blockIdx.x * 256 + threadIdx.x;          // covers D*V exactly
    float x  = W[idx];
    __nv_bfloat16 h = __float2bfloat16_rn(x);
    g_Whi[idx] = h;
    g_Wlo[idx] = __float2bfloat16_rn(x - __bfloat162float(h));
    int d = idx / V_SZ;
    int v = idx - d * V_SZ;
    g_Wt[(size_t)v * D_SZ + d] = x;
}

// ---- K1: dual-pipe GEMM ----------------------------------------------------------
// grid = (42 m-tiles, 10 k-slices), 128 threads, 4 warps (m32 x n64 each)
__global__ __launch_bounds__(128, 3) void gemm_kernel(
    const float* __restrict__ img, const float* __restrict__ tgtim)
{
    extern __shared__ char smem[];
    const u32 sb = smem_u32(smem);
    const int tid  = threadIdx.x;
    const int w    = tid >> 5;
    const int lane = tid & 31;
    const int row0 = blockIdx.x * 128;
    const int ks   = blockIdx.y;
    const int kb   = ks * 2000;

    const float* abase = (blockIdx.x < 40)
        ? img   + (size_t)row0 * V_SZ
        : tgtim + (size_t)(row0 - M_SUP) * V_SZ;

    // tensor-A fill: 16 threads/row (c16 = float4 idx), 8 rows/pass, 16 passes
    const int arow0 = tid >> 4;          // 0..7
    const int c16   = tid & 15;
    // tensor-B fill: 2 threads/row, 4 x 16B each per array
    const int brow  = tid >> 1;          // 0..63
    const int bhalf = tid & 1;
    const char* gwh = (const char*)(g_Whi + (size_t)brow * V_SZ);
    const char* gwl = (const char*)(g_Wlo + (size_t)brow * V_SZ);

    // ldmatrix lane bases (R3/R8-proven)
    const u32 aLB = (u32)(w * 32 + (lane & 15)) * PITCH + (u32)((lane >> 4) * 16);
    const u32 bLB = (u32)((lane & 7) + ((lane >> 4) & 1) * 8) * PITCH
                  + (u32)(((lane >> 3) & 1) * 16);

    // fp32-path addressing
    const int r4 = lane >> 2, c4 = lane & 3;
    const u32 fa0 = sb + OF_FA + (u32)(w * 32 + r4) * FA_P;   // + i*8*FA_P + k*4
    const u32 fb0 = sb + OF_FB + (u32)c4 * 8u;                // + k*256 + nt*32

    // accumulators as f32x2 pairs: [mt][nt][half] (half0=row r, half1=row r+8)
    ull acc[2][8][2];
    #pragma unroll
    for (int mt = 0; mt < 2; ++mt)
        #pragma unroll
        for (int nt = 0; nt < 8; ++nt) { acc[mt][nt][0] = 0ull; acc[mt][nt][1] = 0ull; }

    for (int c = 0; c < NIT; ++c) {
        const int k0   = kb + c * 64;
        const bool fp  = (c < NFP);
        const int kf0  = kb + T_LEN + c * F_LEN;

        __syncthreads();                 // smem free to refill

        // ---- async fills ----
        #pragma unroll
        for (int j = 0; j < 4; ++j) {    // tensor B hi/lo (8 pieces/row, 2 thr/row)
            const int p = bhalf * 4 + j;
            const u32 sB = sb + (u32)brow * PITCH + (u32)p * 16;
            cp16(sB + OF_BHI, gwh + (size_t)k0 * 2 + p * 16);
            cp16(sB + OF_BLO, gwl + (size_t)k0 * 2 + p * 16);
        }
        if (fp) {
            // fp32 A: thread = row, 6 x 16B pieces of [kf0, kf0+24)
            const char* ga = (const char*)(abase + (size_t)tid * V_SZ + kf0);
            const u32 sA = sb + OF_FA + (u32)tid * FA_P;
            #pragma unroll
            for (int p = 0; p < 6; ++p) cp16(sA + p * 16, ga + p * 16);
            // fp32 B: 24 rows x 256B = 384 pieces, 3/thread
            #pragma unroll
            for (int j = 0; j < 3; ++j) {
                const int p = tid + 128 * j;
                const int krow = p >> 4, seg = p & 15;
                cp16(sb + OF_FB + (u32)krow * 256 + (u32)seg * 16,
                     (const char*)(g_Wt + (size_t)(kf0 + krow) * D_SZ) + seg * 16);
            }
        }
        CP_COMMIT();

        // ---- tensor A: LDG fp32 -> split bf16 hi/lo -> STS ----
        #pragma unroll
        for (int j = 0; j < 16; ++j) {
            const int row = arow0 + 8 * j;
            float4 v = *reinterpret_cast<const float4*>(
                abase + (size_t)row * V_SZ + k0 + c16 * 4);
            u32 h0, h1, l0, l1;
            split4(v, h0, h1, l0, l1);
            const u32 sA = sb + (u32)row * PITCH + (u32)c16 * 8;
            sts64(sA,          h0, h1);
            sts64(sA + OF_ALO, l0, l1);
        }

        CP_WAIT0();
        __syncthreads();

        // ---- compute: 4 tensor k16-steps, each followed by 6 fp32 k-steps ----
        #pragma unroll
        for (int s = 0; s < 4; ++s) {
            const u32 so = (u32)s * 32;
            u32 ah[2][4], al[2][4];
            #pragma unroll
            for (int mt = 0; mt < 2; ++mt) {
                u32 a = sb + aLB + (u32)mt * (16 * PITCH) + so;
                ldm4(a,          ah[mt]);
                ldm4(a + OF_ALO, al[mt]);
            }
            #pragma unroll
            for (int q = 0; q < 4; ++q) {
                u32 bh[4], bl[4];
                u32 a = sb + bLB + (u32)q * (16 * PITCH) + so;
                ldm4(a + OF_BHI, bh);
                ldm4(a + OF_BLO, bl);
                #pragma unroll
                for (int mt = 0; mt < 2; ++mt)
                    #pragma unroll
                    for (int h = 0; h < 2; ++h) {
                        ull& c01 = acc[mt][q * 2 + h][0];
                        ull& c23 = acc[mt][q * 2 + h][1];
                        mma2(c01, c23, ah[mt], &bh[2 * h]);
                        mma2(c01, c23, ah[mt], &bl[2 * h]);
                        mma2(c01, c23, al[mt], &bh[2 * h]);
                    }
            }

            // fp32 fma-pipe block: k = s*6 .. s*6+5
            if (fp) {
                #pragma unroll 3
                for (int kk = 0; kk < 6; ++kk) {
                    const int k = s * 6 + kk;
                    ull a0 = dup2(lds32(fa0 + 0u * (8 * FA_P) + (u32)k * 4));
                    ull a1 = dup2(lds32(fa0 + 1u * (8 * FA_P) + (u32)k * 4));
                    ull a2 = dup2(lds32(fa0 + 2u * (8 * FA_P) + (u32)k * 4));
                    ull a3 = dup2(lds32(fa0 + 3u * (8 * FA_P) + (u32)k * 4));
                    const u32 bk = fb0 + (u32)k * 256;
                    #pragma unroll
                    for (int nt = 0; nt < 8; ++nt) {
                        ull b = lds64(bk + (u32)nt * 32);
                        ffma2(acc[0][nt][0], a0, b);
                        ffma2(acc[0][nt][1], a1, b);
                        ffma2(acc[1][nt][0], a2, b);
                        ffma2(acc[1][nt][1], a3, b);
                    }
                }
            }
        }
    }

    // ---- epilogue: store fp32 partials (slice ks) ----
    #pragma unroll
    for (int mt = 0; mt < 2; ++mt) {
        const size_t rg = (size_t)row0 + w * 32 + mt * 16 + r4;
        float* base = &g_part[((size_t)ks * M_ALL + rg) * D_SZ];
        #pragma unroll
        for (int nt = 0; nt < 8; ++nt) {
            float2 f01 = unpack2(acc[mt][nt][0]);
            float2 f23 = unpack2(acc[mt][nt][1]);
            *(float2*)(base + nt * 8 + c4 * 2)                    = f01;
            *(float2*)(base + 8 * (size_t)D_SZ + nt * 8 + c4 * 2) = f23;
        }
    }
}

// ---- K2: reduce k-slices + bias -> g_sup --------------------------------------
__global__ void reduce_kernel(const float* __restrict__ bias) {
    int idx = blockIdx.x * 256 + threadIdx.x;       // covers M_ALL*D exactly
    float s = bias[idx & 63];
    #pragma unroll
    for (int ks = 0; ks < KSPLIT; ++ks)
        s += g_part[(size_t)ks * M_ALL * D_SZ + idx];
    g_sup[idx] = s;
}

// ---- K3: warp-per-episode sims/softmax/preds/argmax/CE ------------------------
__global__ void sim_kernel(const float* __restrict__ onehot,
                           const int* __restrict__ tgty)
{
    const int b    = blockIdx.x;                    // 256 blocks, 32 threads
    const int lane = threadIdx.x;
    const unsigned FULL = 0xFFFFFFFFu;

    const float4* t4 = (const float4*)&g_sup[(size_t)(M_SUP + b) * D_SZ];
    float sim = -3.0e38f;
    if (lane < S_SZ) {
        const float4* s4 = (const float4*)&g_sup[(size_t)(b * S_SZ + lane) * D_SZ];
        float d0 = 0.f, d1 = 0.f, d2 = 0.f, d3 = 0.f;
        float m0 = 0.f, m1 = 0.f, m2 = 0.f, m3 = 0.f;
        #pragma unroll
        for (int i = 0; i < 16; ++i) {
            float4 s = s4[i], t = t4[i];
            d0 += s.x * t.x; d1 += s.y * t.y; d2 += s.z * t.z; d3 += s.w * t.w;
            m0 += s.x * s.x; m1 += s.y * s.y; m2 += s.z * s.z; m3 += s.w * s.w;
        }
        float dot = (d0 + d1) + (d2 + d3);
        float mag = (m0 + m1) + (m2 + m3);
        sim = dot * rsqrtf(fmaxf(mag, 1e-10f));
    }
    float m = sim;
    #pragma unroll
    for (int o = 16; o; o >>= 1) m = fmaxf(m, __shfl_xor_sync(FULL, m, o));
    float e = (lane < S_SZ) ? expf(sim - m) : 0.f;
    float sum = e;
    #pragma unroll
    for (int o = 16; o; o >>= 1) sum += __shfl_xor_sync(FULL, sum, o);
    float attn = e / sum;

    float p = 0.f;
    #pragma unroll
    for (int s = 0; s < S_SZ; ++s) {
        float a = __shfl_sync(FULL, attn, s);
        if (lane < C_SZ) p += a * onehot[((size_t)b * S_SZ + s) * C_SZ + lane];
    }

    float bv = (lane < C_SZ) ? p : -3.0e38f;
    int   bi = (lane < C_SZ) ? lane : 999;
    #pragma unroll
    for (int o = 16; o; o >>= 1) {
        float ov = __shfl_xor_sync(FULL, bv, o);
        int   oi = __shfl_xor_sync(FULL, bi, o);
        if (ov > bv || (ov == bv && oi < bi)) { bv = ov; bi = oi; }
    }
    float pm = (lane < C_SZ) ? p : -3.0e38f;
    #pragma unroll
    for (int o = 16; o; o >>= 1) pm = fmaxf(pm, __shfl_xor_sync(FULL, pm, o));
    float ee = (lane < C_SZ) ? expf(p - pm) : 0.f;
    float lse = ee;
    #pragma unroll
    for (int o = 16; o; o >>= 1) lse += __shfl_xor_sync(FULL, lse, o);

    int y = tgty[b];
    float py = __shfl_sync(FULL, p, y);
    if (lane == 0) {
        g_pb[b]        = (bi == y) ? 1.f : 0.f;
        g_pb[B_SZ + b] = -(py - pm - logf(lse));
    }
}

// ---- K4: deterministic final reduction -> d_out -------------------------------
__global__ void finalize_kernel(float* __restrict__ out) {
    __shared__ float sc[B_SZ], sl[B_SZ];
    int t = threadIdx.x;
    sc[t] = g_pb[t];
    sl[t] = g_pb[B_SZ + t];
    __syncthreads();
    for (int off = 128; off > 0; off >>= 1) {
        if (t < off) { sc[t] += sc[t + off]; sl[t] += sl[t + off]; }
        __syncthreads();
    }
    if (t == 0) {
        out[0] = sc[0] * (1.f / (float)B_SZ);
        out[1] = sl[0] * (1.f / (float)B_SZ);
    }
}

// ---------------------------------------------------------------------------
extern "C" void kernel_launch(void* const* d_in, const int* in_sizes, int n_in,
                              void* d_out, int out_size)
{
    const float* img    = (const float*)d_in[0];   // [256,20,20000]
    const float* onehot = (const float*)d_in[1];   // [256,20,20]
    const float* tgtim  = (const float*)d_in[2];   // [256,20000]
    const int*   tgty   = (const int*)  d_in[3];   // [256]
    const float* W      = (const float*)d_in[4];   // [64,20000]
    const float* bias   = (const float*)d_in[5];   // [64]
    float* out = (float*)d_out;                    // [2]

    cudaFuncSetAttribute(gemm_kernel,
                         cudaFuncAttributeMaxDynamicSharedMemorySize, SMEM_TOTAL);

    prep_w_kernel<<<(D_SZ * V_SZ) / 256, 256>>>(W);
    gemm_kernel<<<dim3(M_ALL / 128, KSPLIT), 128, SMEM_TOTAL>>>(img, tgtim);
    reduce_kernel<<<(M_ALL * D_SZ) / 256, 256>>>(bias);
    sim_kernel<<<B_SZ, 32>>>(onehot, tgty);
    finalize_kernel<<<1, B_SZ>>>(out);
}

// round 12
// speedup vs baseline: 2.6658x; 1.1926x over previous
#include <cuda_runtime.h>
#include <cuda_bf16.h>
#include <cstdint>

// ---------------------------------------------------------------------------
// MatchingNetwork — Round 12: R3 kernel with DE-CHAINED MMA issue order.
// Per k16 step: hoist all ldmatrix, then 3 term-major waves of 16 HMMAs,
// each wave touching 16 DISTINCT accumulators (same-acc distance 1 -> 16).
// ---------------------------------------------------------------------------

#define B_SZ   256
#define S_SZ   20
#define V_SZ   20000
#define C_SZ   20
#define D_SZ   64
#define M_SUP  (B_SZ * S_SZ)      // 5120
#define M_ALL  (M_SUP + B_SZ)     // 5376
#define KSPLIT 7
#define PITCH  176u               // smem row pitch bytes

#define OF_AHI 0u
#define OF_ALO 22528u             // 128*176
#define OF_BHI 45056u
#define OF_BLO 56320u
#define SMEM_TOTAL 67584

typedef uint32_t u32;

// ---- device scratch ---------------------------------------------------------
__device__ float         g_part[(size_t)KSPLIT * M_ALL * D_SZ];
__device__ float         g_sup[(size_t)M_ALL * D_SZ];
__device__ __nv_bfloat16 g_Whi[(size_t)D_SZ * V_SZ];
__device__ __nv_bfloat16 g_Wlo[(size_t)D_SZ * V_SZ];
__device__ float         g_pb[2 * B_SZ];

// ---- PTX helpers ------------------------------------------------------------
__device__ __forceinline__ u32 smem_u32(const void* p) {
    u32 a;
    asm("{ .reg .u64 t; cvta.to.shared.u64 t, %1; cvt.u32.u64 %0, t; }"
        : "=r"(a) : "l"(p));
    return a;
}
__device__ __forceinline__ void sts32(u32 a, u32 v) {
    asm volatile("st.shared.b32 [%0], %1;" :: "r"(a), "r"(v));
}
__device__ __forceinline__ u32 cvt2bf(float lo, float hi) {
    u32 r;
    asm("cvt.rn.bf16x2.f32 %0, %1, %2;" : "=r"(r) : "f"(hi), "f"(lo));
    return r;
}
__device__ __forceinline__ void cp16(u32 s, const void* g) {
    asm volatile("cp.async.cg.shared.global [%0], [%1], 16;" :: "r"(s), "l"(g));
}
#define CP_COMMIT() asm volatile("cp.async.commit_group;" ::: "memory")
#define CP_WAIT0()  asm volatile("cp.async.wait_group 0;" ::: "memory")

__device__ __forceinline__ void ldm4(u32 a, u32 r[4]) {
    asm volatile("ldmatrix.sync.aligned.m8n8.x4.shared.b16 {%0,%1,%2,%3}, [%4];"
        : "=r"(r[0]), "=r"(r[1]), "=r"(r[2]), "=r"(r[3]) : "r"(a));
}
__device__ __forceinline__ void mma16816(float c[4], const u32 a[4],
                                         const u32* b) {
    asm volatile("mma.sync.aligned.m16n8k16.row.col.f32.bf16.bf16.f32 "
        "{%0,%1,%2,%3}, {%4,%5,%6,%7}, {%8,%9}, {%0,%1,%2,%3};"
        : "+f"(c[0]), "+f"(c[1]), "+f"(c[2]), "+f"(c[3])
        : "r"(a[0]), "r"(a[1]), "r"(a[2]), "r"(a[3]), "r"(b[0]), "r"(b[1]));
}

// ---- K0: split W into bf16 hi/lo ---------------------------------------------
__global__ void prep_w_kernel(const float* __restrict__ W) {
    int idx = blockIdx.x * 256 + threadIdx.x;          // covers D*V exactly
    float x  = W[idx];
    __nv_bfloat16 h = __float2bfloat16_rn(x);
    g_Whi[idx] = h;
    g_Wlo[idx] = __float2bfloat16_rn(x - __bfloat162float(h));
}

// ---- K1: split-bf16 HMMA GEMM, de-chained issue order --------------------------
// grid = (42 m-tiles, 7 k-slices), 128 threads (4 warps, warp tile m32 x n64)
__global__ __launch_bounds__(128) void gemm_kernel(
    const float* __restrict__ img, const float* __restrict__ tgtim)
{
    extern __shared__ char smem[];
    const u32 sb = smem_u32(smem);
    const int tid  = threadIdx.x;
    const int w    = tid >> 5;
    const int lane = tid & 31;
    const int row0 = blockIdx.x * 128;
    const int ks   = blockIdx.y;

    // k-slice in k16 steps: 1250 total -> 4x179 + 3x178
    const int sbeg = ks * 178 + (ks < 4 ? ks : 4);
    const int scnt = 178 + (ks < 4 ? 1 : 0);
    const int NCH  = (scnt + 4) / 5;                    // 36 chunks of <=5 steps

    const float* abase = (blockIdx.x < 40)
        ? img   + (size_t)row0 * V_SZ
        : tgtim + (size_t)(row0 - M_SUP) * V_SZ;

    // A fill mapping: 8 passes of 16 rows; 8 threads/row, 5 float2 each
    const int arow_l = tid >> 3;        // 0..15 (+16*pass)
    const int atc    = tid & 7;
    // B fill mapping: 2 threads/row, 5 x 16B each
    const int brow   = tid >> 1;        // 0..63
    const int bhalf  = tid & 1;

    // ldmatrix lane base addresses
    const u32 aLB = (u32)(w * 32 + (lane & 15)) * PITCH
                  + (u32)((lane >> 4) * 16);
    const u32 bLB = (u32)((lane & 7) + ((lane >> 4) & 1) * 8) * PITCH
                  + (u32)(((lane >> 3) & 1) * 16);

    float acc[2][8][4];
    #pragma unroll
    for (int mt = 0; mt < 2; ++mt)
        #pragma unroll
        for (int nt = 0; nt < 8; ++nt)
            #pragma unroll
            for (int i = 0; i < 4; ++i) acc[mt][nt][i] = 0.f;

    for (int c = 0; c < NCH; ++c) {
        const int nk = min(5, scnt - c * 5);            // k16 steps this chunk
        const int k0 = (sbeg + c * 5) * 16;             // element offset

        __syncthreads();                                 // smem free to refill

        // ---- B tiles via cp.async (bf16 hi/lo pre-split in gmem) ----
        {
            const char* gh = (const char*)(g_Whi + (size_t)brow * V_SZ + k0);
            const char* gl = (const char*)(g_Wlo + (size_t)brow * V_SZ + k0);
            u32 sB = sb + (u32)brow * PITCH;
            #pragma unroll
            for (int j = 0; j < 5; ++j) {
                int piece = bhalf * 5 + j;
                if (piece < 2 * nk) {
                    cp16(sB + OF_BHI + piece * 16, gh + piece * 16);
                    cp16(sB + OF_BLO + piece * 16, gl + piece * 16);
                }
            }
            CP_COMMIT();
        }

        // ---- A tiles: LDG fp32 -> split bf16 hi/lo -> STS ----
        #pragma unroll
        for (int p = 0; p < 8; ++p) {
            const int rl = arow_l + p * 16;
            const float2* rp = (const float2*)(abase + (size_t)rl * V_SZ + k0);
            u32 sA = sb + (u32)rl * PITCH;
            #pragma unroll
            for (int j = 0; j < 5; ++j) {
                if (j < nk) {
                    const int c2 = j * 8 + atc;          // float2 index
                    float2 v = rp[c2];
                    u32 h = cvt2bf(v.x, v.y);
                    float r0 = v.x - __uint_as_float(h << 16);
                    float r1 = v.y - __uint_as_float(h & 0xFFFF0000u);
                    u32 l = cvt2bf(r0, r1);
                    sts32(sA + OF_AHI + c2 * 4, h);
                    sts32(sA + OF_ALO + c2 * 4, l);
                }
            }
        }

        CP_WAIT0();
        __syncthreads();

        // ---- MMA over nk k16-steps: hoisted loads, term-major de-chained issue ----
        for (int s = 0; s < nk; ++s) {
            const u32 sbyte = (u32)s * 32;
            u32 ah[2][4], al[2][4];
            #pragma unroll
            for (int mt = 0; mt < 2; ++mt) {
                u32 a = sb + aLB + (u32)mt * (16 * PITCH) + sbyte;
                ldm4(a + OF_AHI, ah[mt]);
                ldm4(a + OF_ALO, al[mt]);
            }
            u32 bh[4][4], bl[4][4];
            #pragma unroll
            for (int q = 0; q < 4; ++q) {
                u32 a = sb + bLB + (u32)q * (16 * PITCH) + sbyte;
                ldm4(a + OF_BHI, bh[q]);
                ldm4(a + OF_BLO, bl[q]);
            }
            // term 1: Ah * Bh — 16 distinct accumulators
            #pragma unroll
            for (int q = 0; q < 4; ++q)
                #pragma unroll
                for (int mt = 0; mt < 2; ++mt)
                    #pragma unroll
                    for (int h = 0; h < 2; ++h)
                        mma16816(acc[mt][q * 2 + h], ah[mt], &bh[q][2 * h]);
            // term 2: Ah * Bl
            #pragma unroll
            for (int q = 0; q < 4; ++q)
                #pragma unroll
                for (int mt = 0; mt < 2; ++mt)
                    #pragma unroll
                    for (int h = 0; h < 2; ++h)
                        mma16816(acc[mt][q * 2 + h], ah[mt], &bl[q][2 * h]);
            // term 3: Al * Bh
            #pragma unroll
            for (int q = 0; q < 4; ++q)
                #pragma unroll
                for (int mt = 0; mt < 2; ++mt)
                    #pragma unroll
                    for (int h = 0; h < 2; ++h)
                        mma16816(acc[mt][q * 2 + h], al[mt], &bh[q][2 * h]);
        }
    }

    // ---- epilogue: store partials ----
    const int r4 = lane >> 2, c4 = lane & 3;
    #pragma unroll
    for (int mt = 0; mt < 2; ++mt) {
        const size_t rg = (size_t)row0 + w * 32 + mt * 16 + r4;
        float* base = &g_part[((size_t)ks * M_ALL + rg) * D_SZ];
        #pragma unroll
        for (int nt = 0; nt < 8; ++nt) {
            float2 v0 = make_float2(acc[mt][nt][0], acc[mt][nt][1]);
            float2 v1 = make_float2(acc[mt][nt][2], acc[mt][nt][3]);
            *(float2*)(base + nt * 8 + c4 * 2)                 = v0;
            *(float2*)(base + 8 * (size_t)D_SZ + nt * 8 + c4 * 2) = v1;
        }
    }
}

// ---- K2: reduce k-slices + bias -> g_sup --------------------------------------
__global__ void reduce_kernel(const float* __restrict__ bias) {
    int idx = blockIdx.x * 256 + threadIdx.x;          // covers M_ALL*D exactly
    float s = bias[idx & 63];
    #pragma unroll
    for (int ks = 0; ks < KSPLIT; ++ks)
        s += g_part[(size_t)ks * M_ALL * D_SZ + idx];
    g_sup[idx] = s;
}

// ---- K3: warp-per-episode sims/softmax/preds/argmax/CE ------------------------
__global__ void sim_kernel(const float* __restrict__ onehot,
                           const int* __restrict__ tgty)
{
    const int b    = blockIdx.x;                    // 256 blocks, 32 threads
    const int lane = threadIdx.x;
    const unsigned FULL = 0xFFFFFFFFu;

    const float4* t4 = (const float4*)&g_sup[(size_t)(M_SUP + b) * D_SZ];
    float sim = -3.0e38f;
    if (lane < S_SZ) {
        const float4* s4 = (const float4*)&g_sup[(size_t)(b * S_SZ + lane) * D_SZ];
        float d0 = 0.f, d1 = 0.f, d2 = 0.f, d3 = 0.f;
        float m0 = 0.f, m1 = 0.f, m2 = 0.f, m3 = 0.f;
        #pragma unroll
        for (int i = 0; i < 16; ++i) {
            float4 s = s4[i], t = t4[i];
            d0 += s.x * t.x; d1 += s.y * t.y; d2 += s.z * t.z; d3 += s.w * t.w;
            m0 += s.x * s.x; m1 += s.y * s.y; m2 += s.z * s.z; m3 += s.w * s.w;
        }
        float dot = (d0 + d1) + (d2 + d3);
        float mag = (m0 + m1) + (m2 + m3);
        sim = dot * rsqrtf(fmaxf(mag, 1e-10f));
    }
    float m = sim;
    #pragma unroll
    for (int o = 16; o; o >>= 1) m = fmaxf(m, __shfl_xor_sync(FULL, m, o));
    float e = (lane < S_SZ) ? expf(sim - m) : 0.f;
    float sum = e;
    #pragma unroll
    for (int o = 16; o; o >>= 1) sum += __shfl_xor_sync(FULL, sum, o);
    float attn = e / sum;

    float p = 0.f;
    #pragma unroll
    for (int s = 0; s < S_SZ; ++s) {
        float a = __shfl_sync(FULL, attn, s);
        if (lane < C_SZ) p += a * onehot[((size_t)b * S_SZ + s) * C_SZ + lane];
    }

    float bv = (lane < C_SZ) ? p : -3.0e38f;
    int   bi = (lane < C_SZ) ? lane : 999;
    #pragma unroll
    for (int o = 16; o; o >>= 1) {
        float ov = __shfl_xor_sync(FULL, bv, o);
        int   oi = __shfl_xor_sync(FULL, bi, o);
        if (ov > bv || (ov == bv && oi < bi)) { bv = ov; bi = oi; }
    }
    float pm = (lane < C_SZ) ? p : -3.0e38f;
    #pragma unroll
    for (int o = 16; o; o >>= 1) pm = fmaxf(pm, __shfl_xor_sync(FULL, pm, o));
    float ee = (lane < C_SZ) ? expf(p - pm) : 0.f;
    float lse = ee;
    #pragma unroll
    for (int o = 16; o; o >>= 1) lse += __shfl_xor_sync(FULL, lse, o);

    int y = tgty[b];
    float py = __shfl_sync(FULL, p, y);
    if (lane == 0) {
        g_pb[b]        = (bi == y) ? 1.f : 0.f;
        g_pb[B_SZ + b] = -(py - pm - logf(lse));
    }
}

// ---- K4: deterministic final reduction -> d_out -------------------------------
__global__ void finalize_kernel(float* __restrict__ out) {
    __shared__ float sc[B_SZ], sl[B_SZ];
    int t = threadIdx.x;
    sc[t] = g_pb[t];
    sl[t] = g_pb[B_SZ + t];
    __syncthreads();
    for (int off = 128; off > 0; off >>= 1) {
        if (t < off) { sc[t] += sc[t + off]; sl[t] += sl[t + off]; }
        __syncthreads();
    }
    if (t == 0) {
        out[0] = sc[0] * (1.f / (float)B_SZ);
        out[1] = sl[0] * (1.f / (float)B_SZ);
    }
}

// ---------------------------------------------------------------------------
extern "C" void kernel_launch(void* const* d_in, const int* in_sizes, int n_in,
                              void* d_out, int out_size)
{
    const float* img    = (const float*)d_in[0];   // [256,20,20000]
    const float* onehot = (const float*)d_in[1];   // [256,20,20]
    const float* tgtim  = (const float*)d_in[2];   // [256,20000]
    const int*   tgty   = (const int*)  d_in[3];   // [256]
    const float* W      = (const float*)d_in[4];   // [64,20000]
    const float* bias   = (const float*)d_in[5];   // [64]
    float* out = (float*)d_out;                    // [2]

    cudaFuncSetAttribute(gemm_kernel,
                         cudaFuncAttributeMaxDynamicSharedMemorySize, SMEM_TOTAL);

    prep_w_kernel<<<(D_SZ * V_SZ) / 256, 256>>>(W);
    gemm_kernel<<<dim3(M_ALL / 128, KSPLIT), 128, SMEM_TOTAL>>>(img, tgtim);
    reduce_kernel<<<(M_ALL * D_SZ) / 256, 256>>>(bias);
    sim_kernel<<<B_SZ, 32>>>(onehot, tgty);
    finalize_kernel<<<1, B_SZ>>>(out);
}